// round 5
// baseline (speedup 1.0000x reference)
#include <cuda_runtime.h>

typedef unsigned long long ull;

static constexpr int B = 32;
static constexpr int T = 32768;
static constexpr int H = 64;

__device__ __forceinline__ void fma2(ull& acc, ull a, ull b) {
    asm("fma.rn.f32x2 %0, %1, %2, %0;" : "+l"(acc) : "l"(a), "l"(b));
}
__device__ __forceinline__ void add2(ull& a, ull b) {
    asm("add.rn.f32x2 %0, %1, %2;" : "=l"(a) : "l"(a), "l"(b));
}
__device__ __forceinline__ ull pack2(float lo, float hi) {
    ull v;
    asm("mov.b64 %0, {%1,%2};" : "=l"(v) : "f"(lo), "f"(hi));
    return v;
}
__device__ __forceinline__ float sum2(ull v) {
    float lo, hi;
    asm("mov.b64 {%0,%1}, %2;" : "=f"(lo), "=f"(hi) : "l"(v));
    return lo + hi;
}
__device__ __forceinline__ float rcpf(float x) {
    float r;
    asm("rcp.approx.ftz.f32 %0, %1;" : "=f"(r) : "f"(x));
    return r;
}
__device__ __forceinline__ float ex2f(float x) {
    float r;
    asm("ex2.approx.ftz.f32 %0, %1;" : "=f"(r) : "f"(x));
    return r;
}

// Scales folded into weights so EX2 gets its argument straight from the dot:
//   sigma(v) = 1/(1 + 2^(-v*log2e))           -> gate rows scaled by S1
//   tanh(v)  = (1-e)/(1+e), e = 2^(-2v*log2e) -> n row scaled by S2
static constexpr float S1 = -1.4426950408889634f;   // -log2(e)
static constexpr float S2 = -2.8853900817779268f;   // -2 log2(e)

// One CTA per batch, 256 threads. Quad (4 lanes) per hidden element i:
//   j=0: r-dot K[0:32)  + n-dot K[0:32)
//   j=1: r-dot K[32:64) + n-dot K[32:64)
//   j=2: z-dot K[0:32)  + n-dot K[0:32)   (n redundant across pairs)
//   j=3: z-dot K[32:64) + n-dot K[32:64)
// Pair reduce = shfl_xor(1); z reaches the r-pair via shfl_xor(2).
// Identical instruction stream on all lanes; one __syncthreads per step.
__global__ __launch_bounds__(256, 1)
void gru_kernel(const float* __restrict__ x,
                const float* __restrict__ w_ih,
                const float* __restrict__ w_hh,
                const float* __restrict__ b_ih,
                const float* __restrict__ b_hh,
                float* __restrict__ states)   // [B, T, H]
{
    __shared__ __align__(16) float h_sh[2][64];

    const int bb  = blockIdx.x;
    const int tid = threadIdx.x;
    const int i   = tid >> 2;       // hidden element 0..63
    const int j   = tid & 3;        // lane-in-quad
    const int kof = (j & 1) * 32;   // K-half
    const int grow = i + ((j >> 1) ? 64 : 0);   // r row (j<2) or z row (j>=2)

    // --- stationary, pre-scaled weights in registers ---
    ull wg[16], wn[16];
    {
        const float* pg = w_hh + (size_t)grow * H + kof;
        const float* pn = w_hh + (size_t)(i + 128) * H + kof;
        #pragma unroll
        for (int m = 0; m < 16; m++) {
            wg[m] = pack2(pg[2 * m] * S1, pg[2 * m + 1] * S1);
            wn[m] = pack2(pn[2 * m] * S2, pn[2 * m + 1] * S2);
        }
    }
    const float wihg_s = w_ih[grow] * S1;
    const float bg_s   = (b_ih[grow] + b_hh[grow]) * S1;
    const float wihn_s = w_ih[i + 128] * S2;
    const float bihn_s = b_ih[i + 128] * S2;
    // bhh_n sits inside the r-multiplied term -> seed it into the n-dot,
    // exactly once per pair (lanes j=0 and j=2 seed their pair's sum).
    const float seed_n = (j & 1) ? 0.f : b_hh[i + 128] * S2;
    const float seed_g_mask = (j & 1) ? 0.f : 1.f;

    if (tid < 64) { h_sh[0][tid] = 0.f; h_sh[1][tid] = 0.f; }
    __syncthreads();

    const float* xb = x + (size_t)bb * T;
    float* sb = states + (size_t)bb * T * H + i;

    float h_prev = 0.f;   // meaningful on lanes j<2

// NOTE: no local may shadow the loop counter that TT expands to.
#define GRU_STEP(XT, RB, WB, TT)                                              \
    do {                                                                      \
        float xg = fmaf((XT), wihg_s, bg_s) * seed_g_mask;                    \
        float xnl = fmaf((XT), wihn_s, bihn_s);                               \
        const ulonglong2* hv = (const ulonglong2*)(h_sh[RB] + kof);           \
        ulonglong2 hA = hv[0], hB = hv[1], hC = hv[2], hD = hv[3];            \
        ull g0 = pack2(xg, 0.f), g1 = 0, g2 = 0, g3 = 0;                      \
        fma2(g0, wg[ 0], hA.x); fma2(g1, wg[ 1], hA.y);                       \
        fma2(g2, wg[ 2], hB.x); fma2(g3, wg[ 3], hB.y);                       \
        fma2(g0, wg[ 4], hC.x); fma2(g1, wg[ 5], hC.y);                       \
        fma2(g2, wg[ 6], hD.x); fma2(g3, wg[ 7], hD.y);                       \
        const ulonglong2* hvq = hv + 4;                                       \
        ulonglong2 hE = hvq[0], hF = hvq[1], hG = hvq[2], hHH = hvq[3];       \
        fma2(g0, wg[ 8], hE.x); fma2(g1, wg[ 9], hE.y);                       \
        fma2(g2, wg[10], hF.x); fma2(g3, wg[11], hF.y);                       \
        fma2(g0, wg[12], hG.x); fma2(g1, wg[13], hG.y);                       \
        fma2(g2, wg[14], hHH.x); fma2(g3, wg[15], hHH.y);                     \
        add2(g0, g1); add2(g2, g3); add2(g0, g2);                             \
        float gsum = sum2(g0);                                                \
        float gful = gsum + __shfl_xor_sync(0xffffffffu, gsum, 1);            \
        float ge = ex2f(gful);                                                \
        float g  = rcpf(1.f + ge);          /* r on j<2, z on j>=2 */         \
        ull n0 = pack2(seed_n, 0.f), n1 = 0, n2 = 0, n3 = 0;                  \
        fma2(n0, wn[ 0], hA.x); fma2(n1, wn[ 1], hA.y);                       \
        fma2(n2, wn[ 2], hB.x); fma2(n3, wn[ 3], hB.y);                       \
        fma2(n0, wn[ 4], hC.x); fma2(n1, wn[ 5], hC.y);                       \
        fma2(n2, wn[ 6], hD.x); fma2(n3, wn[ 7], hD.y);                       \
        fma2(n0, wn[ 8], hE.x); fma2(n1, wn[ 9], hE.y);                       \
        fma2(n2, wn[10], hF.x); fma2(n3, wn[11], hF.y);                       \
        fma2(n0, wn[12], hG.x); fma2(n1, wn[13], hG.y);                       \
        fma2(n2, wn[14], hHH.x); fma2(n3, wn[15], hHH.y);                     \
        add2(n0, n1); add2(n2, n3); add2(n0, n2);                             \
        float nsum = sum2(n0);                                                \
        float cn = nsum + __shfl_xor_sync(0xffffffffu, nsum, 1);              \
        float un = fminf(fmaf(g, cn, xnl), 126.f);                            \
        float ne = ex2f(un);                                                  \
        float nr = rcpf(1.f + ne);                                            \
        float th = fmaf(-2.f * ne, nr, 1.f);   /* tanh(n-arg) on j<2 */       \
        float zz = __shfl_xor_sync(0xffffffffu, g, 2);  /* sigma(z) to j<2 */ \
        float hnew = fmaf(zz, h_prev - th, th);                               \
        h_prev = hnew;                                                        \
        if (j == 0) h_sh[WB][i] = hnew;                                       \
        if (j == 1) sb[(size_t)(TT) * H] = hnew;                              \
        __syncthreads();                                                      \
    } while (0)

    float x0 = __ldg(xb);
    for (int t = 0; t < T; t += 2) {
        float x1 = __ldg(xb + t + 1);
        int tn = (t + 2 < T) ? (t + 2) : (T - 1);
        float xnxt = __ldg(xb + tn);
        GRU_STEP(x0, 0, 1, t);
        GRU_STEP(x1, 1, 0, t + 1);
        x0 = xnxt;
    }
#undef GRU_STEP
}

// out[b,t] = dot(states[b,t,:], w_lin) + b_lin + x[b,t]  — parallel epilogue
__global__ __launch_bounds__(256)
void head_kernel(const float* __restrict__ x,
                 const float* __restrict__ states,
                 const float* __restrict__ w_lin,
                 const float* __restrict__ b_lin,
                 float* __restrict__ out)
{
    int idx = blockIdx.x * blockDim.x + threadIdx.x;   // 0 .. B*T-1 exactly
    const float4* s4 = (const float4*)(states + (size_t)idx * H);
    const float4* w4 = (const float4*)w_lin;
    float acc = 0.f;
    #pragma unroll
    for (int m = 0; m < 16; m++) {
        float4 s = __ldg(&s4[m]);
        float4 w = __ldg(&w4[m]);
        acc = fmaf(s.x, w.x, acc);
        acc = fmaf(s.y, w.y, acc);
        acc = fmaf(s.z, w.z, acc);
        acc = fmaf(s.w, w.w, acc);
    }
    out[idx] = acc + __ldg(b_lin) + __ldg(&x[idx]);
}

extern "C" void kernel_launch(void* const* d_in, const int* in_sizes, int n_in,
                              void* d_out, int out_size)
{
    const float* x     = (const float*)d_in[0];
    const float* w_ih  = (const float*)d_in[1];
    const float* w_hh  = (const float*)d_in[2];
    const float* b_ih  = (const float*)d_in[3];
    const float* b_hh  = (const float*)d_in[4];
    const float* w_lin = (const float*)d_in[5];
    const float* b_lin = (const float*)d_in[6];

    float* out    = (float*)d_out;                 // [B, T]
    float* states = out + (size_t)B * T;           // [B, T, H]

    gru_kernel<<<B, 256>>>(x, w_ih, w_hh, b_ih, b_hh, states);
    head_kernel<<<(B * T) / 256, 256>>>(x, states, w_lin, b_lin, out);
}

// round 6
// speedup vs baseline: 1.5944x; 1.5944x over previous
#include <cuda_runtime.h>

typedef unsigned long long ull;

static constexpr int B = 32;
static constexpr int T = 32768;
static constexpr int H = 64;

__device__ __forceinline__ void fma2(ull& acc, ull a, ull b) {
    asm("fma.rn.f32x2 %0, %1, %2, %0;" : "+l"(acc) : "l"(a), "l"(b));
}
__device__ __forceinline__ void add2(ull& a, ull b) {
    asm("add.rn.f32x2 %0, %1, %2;" : "=l"(a) : "l"(a), "l"(b));
}
__device__ __forceinline__ ull pack2(float lo, float hi) {
    ull v;
    asm("mov.b64 %0, {%1,%2};" : "=l"(v) : "f"(lo), "f"(hi));
    return v;
}
__device__ __forceinline__ float sum2(ull v) {
    float lo, hi;
    asm("mov.b64 {%0,%1}, %2;" : "=f"(lo), "=f"(hi) : "l"(v));
    return lo + hi;
}
__device__ __forceinline__ float rcpf(float x) {
    float r;
    asm("rcp.approx.ftz.f32 %0, %1;" : "=f"(r) : "f"(x));
    return r;
}
__device__ __forceinline__ float ex2f(float x) {
    float r;
    asm("ex2.approx.ftz.f32 %0, %1;" : "=f"(r) : "f"(x));
    return r;
}

// -log2(e) folded into gate rows, -2log2(e) into n row, so EX2 consumes the
// dot product directly:  sigma(v)=1/(1+2^(S1*v)),  tanh via e=2^(S2*v).
static constexpr float S1 = -1.4426950408889634f;
static constexpr float S2 = -2.8853900817779268f;

// One CTA per batch, 128 threads. Pair (2i,2i+1) owns hidden element i.
// Even lane: full-K r-dot (no shfl before sigma) + n-dot K[0:32).
// Odd lane:  full-K z-dot + n-dot K[32:64).
// z reaches the even lane via one late shfl. One __syncthreads per step.
__global__ __launch_bounds__(128, 1)
void gru_kernel(const float* __restrict__ x,
                const float* __restrict__ w_ih,
                const float* __restrict__ w_hh,
                const float* __restrict__ b_ih,
                const float* __restrict__ b_hh,
                float* __restrict__ states)   // [B, T, H]
{
    __shared__ __align__(16) float h_sh[2][64];

    const int bb  = blockIdx.x;
    const int tid = threadIdx.x;
    const int i   = tid >> 1;      // hidden element 0..63
    const int hk  = tid & 1;       // 0 -> r row, 1 -> z row; also n K-half

    // stationary weights in registers, pre-scaled
    ull w0[32], wn[16];
    {
        const int r0 = i + hk * 64;                      // r or z row
        const float* p0 = w_hh + (size_t)r0 * H;
        #pragma unroll
        for (int m = 0; m < 32; m++)
            w0[m] = pack2(p0[2 * m] * S1, p0[2 * m + 1] * S1);
        const float* pn = w_hh + (size_t)(i + 128) * H + 32 * hk;
        #pragma unroll
        for (int m = 0; m < 16; m++)
            wn[m] = pack2(pn[2 * m] * S2, pn[2 * m + 1] * S2);
    }
    const int idx0 = i + hk * 64;
    const float wih0_s = w_ih[idx0] * S1;
    const float b0_s   = (b_ih[idx0] + b_hh[idx0]) * S1;
    const float wihn_s = w_ih[i + 128] * S2;
    const float bihn_s = b_ih[i + 128] * S2;
    const float seed_n = hk ? 0.f : b_hh[i + 128] * S2;  // once per pair

    if (tid < 64) { h_sh[0][tid] = 0.f; h_sh[1][tid] = 0.f; }
    __syncthreads();

    const float* xb = x + (size_t)bb * T;
    float* sb = states + (size_t)bb * T * H + i;

    float h_prev = 0.f;   // meaningful on even lane only

// NOTE: no local may shadow the loop counter that TT expands to.
#define GRU_STEP(XT, RB, WB, TT)                                              \
    do {                                                                      \
        float xg  = fmaf((XT), wih0_s, b0_s);                                 \
        float xnl = fmaf((XT), wihn_s, bihn_s);                               \
        const ulonglong2* hv2 = (const ulonglong2*)h_sh[RB];                  \
        ull a0 = pack2(xg, 0.f), a1 = 0, a2 = 0, a3 = 0;                      \
        _Pragma("unroll")                                                     \
        for (int m = 0; m < 16; m += 2) {   /* all 64 h */                    \
            ulonglong2 hA = hv2[m], hB = hv2[m + 1];                          \
            fma2(a0, w0[2 * m + 0], hA.x); fma2(a1, w0[2 * m + 1], hA.y);     \
            fma2(a2, w0[2 * m + 2], hB.x); fma2(a3, w0[2 * m + 3], hB.y);     \
        }                                                                     \
        add2(a0, a1); add2(a2, a3); add2(a0, a2);                             \
        float gful = sum2(a0);                                                \
        float ge = ex2f(gful);                                                \
        float g  = rcpf(1.f + ge);          /* r (even) / z (odd) */          \
        const ulonglong2* hn2 = (const ulonglong2*)(h_sh[RB] + 32 * hk);      \
        ull n0 = pack2(seed_n, 0.f), n1 = 0;                                  \
        _Pragma("unroll")                                                     \
        for (int m = 0; m < 8; m++) {       /* 32 h (K-half) */               \
            ulonglong2 hC = hn2[m];                                           \
            fma2(n0, wn[2 * m + 0], hC.x);                                    \
            fma2(n1, wn[2 * m + 1], hC.y);                                    \
        }                                                                     \
        add2(n0, n1);                                                         \
        float cnh = sum2(n0);                                                 \
        float cn  = cnh + __shfl_xor_sync(0xffffffffu, cnh, 1);               \
        float un  = fminf(fmaf(g, cn, xnl), 60.f);                            \
        float ne  = ex2f(un);                                                 \
        float nr  = rcpf(1.f + ne);                                           \
        float th  = fmaf(-2.f * ne, nr, 1.f);  /* tanh on even lane */        \
        float zz  = __shfl_xor_sync(0xffffffffu, g, 1);                       \
        float hnew = fmaf(zz, h_prev - th, th);                               \
        h_prev = hnew;                                                        \
        if (!hk) { h_sh[WB][i] = hnew; sb[(size_t)(TT) * H] = hnew; }         \
        __syncthreads();                                                      \
    } while (0)

    float x0 = __ldg(xb);
    for (int t = 0; t < T; t += 2) {
        float x1 = __ldg(xb + t + 1);
        int tn = (t + 2 < T) ? (t + 2) : (T - 1);
        float xnxt = __ldg(xb + tn);
        GRU_STEP(x0, 0, 1, t);
        GRU_STEP(x1, 1, 0, t + 1);
        x0 = xnxt;
    }
#undef GRU_STEP
}

// out[b,t] = dot(states[b,t,:], w_lin) + b_lin + x[b,t]  — parallel epilogue
__global__ __launch_bounds__(256)
void head_kernel(const float* __restrict__ x,
                 const float* __restrict__ states,
                 const float* __restrict__ w_lin,
                 const float* __restrict__ b_lin,
                 float* __restrict__ out)
{
    int idx = blockIdx.x * blockDim.x + threadIdx.x;   // 0 .. B*T-1 exactly
    const float4* s4 = (const float4*)(states + (size_t)idx * H);
    const float4* w4 = (const float4*)w_lin;
    float acc = 0.f;
    #pragma unroll
    for (int m = 0; m < 16; m++) {
        float4 s = __ldg(&s4[m]);
        float4 w = __ldg(&w4[m]);
        acc = fmaf(s.x, w.x, acc);
        acc = fmaf(s.y, w.y, acc);
        acc = fmaf(s.z, w.z, acc);
        acc = fmaf(s.w, w.w, acc);
    }
    out[idx] = acc + __ldg(b_lin) + __ldg(&x[idx]);
}

// No-op spacers: shift launch indices so ncu's "-s 5 -c 1" captures
// gru_kernel (launch order per call: nop, gru, nop, head -> global launch
// index 5 = replay#1's gru). Negligible graph-node overhead.
__global__ void nop_kernel() {}

extern "C" void kernel_launch(void* const* d_in, const int* in_sizes, int n_in,
                              void* d_out, int out_size)
{
    const float* x     = (const float*)d_in[0];
    const float* w_ih  = (const float*)d_in[1];
    const float* w_hh  = (const float*)d_in[2];
    const float* b_ih  = (const float*)d_in[3];
    const float* b_hh  = (const float*)d_in[4];
    const float* w_lin = (const float*)d_in[5];
    const float* b_lin = (const float*)d_in[6];

    float* out    = (float*)d_out;                 // [B, T]
    float* states = out + (size_t)B * T;           // [B, T, H]

    nop_kernel<<<1, 32>>>();
    gru_kernel<<<B, 128>>>(x, w_ih, w_hh, b_ih, b_hh, states);
    nop_kernel<<<1, 32>>>();
    head_kernel<<<(B * T) / 256, 256>>>(x, states, w_lin, b_lin, out);
}